// round 1
// baseline (speedup 1.0000x reference)
#include <cuda_runtime.h>
#include <cuda_bf16.h>
#include <math.h>

// Problem dims (fixed by the reference)
#define BB 2
#define SS 2048
#define DD 1024
#define HH 16
#define DHH 64
#define FF 4096
#define NTOK (BB*SS)   // 4096 tokens

// ---------------- scratch (device globals; no allocations allowed) -----------
__device__ float g_h   [NTOK*DD];   // ln1 output
__device__ float g_q   [NTOK*DD];
__device__ float g_k   [NTOK*DD];
__device__ float g_v   [NTOK*DD];
__device__ float g_o   [NTOK*DD];   // attention output (pre O-proj)
__device__ float g_add1[NTOK*DD];   // x + attn_out
__device__ float g_h2  [NTOK*DD];   // ln2 output
__device__ float g_act [NTOK*FF];   // gelu(h2@w1+b1)

// ---------------- LayerNorm: one block per row of 1024 ----------------------
__global__ void ln_kernel(const float* __restrict__ x,
                          const float* __restrict__ g,
                          const float* __restrict__ b,
                          float* __restrict__ y) {
    const int row = blockIdx.x;
    const int tid = threadIdx.x;           // 256 threads
    const float* xr = x + (size_t)row * DD;
    float* yr = y + (size_t)row * DD;

    float v[4];
    float s = 0.f, s2 = 0.f;
#pragma unroll
    for (int i = 0; i < 4; ++i) {
        v[i] = xr[tid + i * 256];
        s += v[i];
        s2 += v[i] * v[i];
    }
    // warp reduce
    for (int off = 16; off > 0; off >>= 1) {
        s  += __shfl_down_sync(0xffffffffu, s,  off);
        s2 += __shfl_down_sync(0xffffffffu, s2, off);
    }
    __shared__ float rs[8], rs2[8];
    if ((tid & 31) == 0) { rs[tid >> 5] = s; rs2[tid >> 5] = s2; }
    __syncthreads();
    if (tid < 8) { s = rs[tid]; s2 = rs2[tid]; }
    else         { s = 0.f; s2 = 0.f; }
    if (tid < 32) {
        for (int off = 4; off > 0; off >>= 1) {
            s  += __shfl_down_sync(0xffffffffu, s,  off);
            s2 += __shfl_down_sync(0xffffffffu, s2, off);
        }
        if (tid == 0) { rs[0] = s; rs2[0] = s2; }
    }
    __syncthreads();
    const float mean = rs[0] * (1.0f / DD);
    const float var  = rs2[0] * (1.0f / DD) - mean * mean;
    const float inv  = rsqrtf(var + 1e-5f);
#pragma unroll
    for (int i = 0; i < 4; ++i) {
        const int c = tid + i * 256;
        yr[c] = (v[i] - mean) * inv * g[c] + b[c];
    }
}

// ---------------- Tiled SGEMM: C[M,N] = A[M,K] @ B[K,N] (+bias)(gelu)(+res) --
// BM=BN=128, BK=16, 256 threads, 8x8 microtile. M,N,K multiples of 128 here.
template<bool HAS_RES, bool DO_GELU>
__global__ void __launch_bounds__(256)
sgemm_kernel(const float* __restrict__ A, const float* __restrict__ B,
             const float* __restrict__ bias, const float* __restrict__ res,
             float* __restrict__ C, int M, int N, int K) {
    __shared__ float As[16][128];
    __shared__ float Bs[16][132];   // padded rows

    const int tid = threadIdx.x;
    const int bx = blockIdx.x;      // N tile
    const int by = blockIdx.y;      // M tile

    const float* Ab = A + (size_t)by * 128 * K;
    const float* Bb = B + (size_t)bx * 128;

    const int arow = tid >> 2;          // 0..63
    const int acol = (tid & 3) * 4;     // 0,4,8,12
    const int brow = tid >> 5;          // 0..7
    const int bcol = (tid & 31) * 4;    // 0..124

    const int tr = (tid >> 4) * 8;      // C row offset in tile
    const int tc = (tid & 15) * 8;      // C col offset in tile

    float acc[8][8];
#pragma unroll
    for (int i = 0; i < 8; ++i)
#pragma unroll
        for (int j = 0; j < 8; ++j) acc[i][j] = 0.f;

    for (int k0 = 0; k0 < K; k0 += 16) {
#pragma unroll
        for (int hh = 0; hh < 2; ++hh) {
            const int r = arow + hh * 64;
            float4 va = *(const float4*)(Ab + (size_t)r * K + k0 + acol);
            As[acol + 0][r] = va.x;
            As[acol + 1][r] = va.y;
            As[acol + 2][r] = va.z;
            As[acol + 3][r] = va.w;
        }
#pragma unroll
        for (int hh = 0; hh < 2; ++hh) {
            const int r = brow + hh * 8;
            float4 vb = *(const float4*)(Bb + (size_t)(k0 + r) * N + bcol);
            *(float4*)(&Bs[r][bcol]) = vb;
        }
        __syncthreads();
#pragma unroll
        for (int kk = 0; kk < 16; ++kk) {
            float ra[8], rb[8];
#pragma unroll
            for (int i = 0; i < 8; ++i) ra[i] = As[kk][tr + i];
            float4 b0 = *(const float4*)(&Bs[kk][tc]);
            float4 b1 = *(const float4*)(&Bs[kk][tc + 4]);
            rb[0]=b0.x; rb[1]=b0.y; rb[2]=b0.z; rb[3]=b0.w;
            rb[4]=b1.x; rb[5]=b1.y; rb[6]=b1.z; rb[7]=b1.w;
#pragma unroll
            for (int i = 0; i < 8; ++i)
#pragma unroll
                for (int j = 0; j < 8; ++j) acc[i][j] = fmaf(ra[i], rb[j], acc[i][j]);
        }
        __syncthreads();
    }

    const int row0 = by * 128 + tr;
    const int col0 = bx * 128 + tc;
#pragma unroll
    for (int i = 0; i < 8; ++i) {
        const size_t roff = (size_t)(row0 + i) * N + col0;
#pragma unroll
        for (int j = 0; j < 8; ++j) {
            float vv = acc[i][j] + bias[col0 + j];
            if (DO_GELU) vv = 0.5f * vv * (1.0f + erff(vv * 0.70710678118654752f));
            if (HAS_RES) vv += res[roff + j];
            C[roff + j] = vv;
        }
    }
}

// ---------------- Flash attention (fp32, causal) -----------------------------
// grid: (S/64, B*H); block 256. q/k/v/o in token-major [NTOK, D] layout,
// head h occupies columns [h*64, h*64+64).
__global__ void __launch_bounds__(256)
attn_kernel(const float* __restrict__ q, const float* __restrict__ k,
            const float* __restrict__ v, float* __restrict__ o) {
    const int qt = blockIdx.x;          // query tile (64 queries)
    const int bh = blockIdx.y;
    const int b = bh / HH, h = bh % HH;
    const size_t base = (size_t)b * SS * DD + (size_t)h * DHH;
    const float* qb = q + base;
    const float* kb = k + base;
    const float* vb = v + base;
    float* ob = o + base;

    __shared__ float Qs[64][65];
    __shared__ float Ks[32][65];
    __shared__ float Vs[32][65];
    __shared__ float Ps[64][33];
    __shared__ float m_s[64], l_s[64], a_s[64];

    const int tid = threadIdx.x;
    const int q0 = qt * 64;

    // load Q tile (64x64)
#pragma unroll
    for (int i = 0; i < 4; ++i) {
        const int lin = tid + i * 256;
        const int r = lin >> 4, c = (lin & 15) * 4;
        float4 vq = *(const float4*)(qb + (size_t)(q0 + r) * DD + c);
        Qs[r][c + 0] = vq.x; Qs[r][c + 1] = vq.y;
        Qs[r][c + 2] = vq.z; Qs[r][c + 3] = vq.w;
    }
    if (tid < 64) { m_s[tid] = -3.0e38f; l_s[tid] = 0.f; }

    const int tq0 = (tid >> 4) * 4;     // 4 query rows
    const int tk0 = (tid & 15) * 2;     // 2 key cols (scores)
    const int tc0 = (tid & 15) * 4;     // 4 dh cols (output)

    float oacc[4][4];
#pragma unroll
    for (int i = 0; i < 4; ++i)
#pragma unroll
        for (int j = 0; j < 4; ++j) oacc[i][j] = 0.f;

    const int ntiles = qt * 2 + 2;      // key tiles of 32 covering [0, q0+64)
    for (int kt = 0; kt < ntiles; ++kt) {
        __syncthreads();
        // load K,V tiles (32x64 each)
#pragma unroll
        for (int i = 0; i < 2; ++i) {
            const int lin = tid + i * 256;
            const int r = lin >> 4, c = (lin & 15) * 4;
            float4 vk = *(const float4*)(kb + (size_t)(kt * 32 + r) * DD + c);
            Ks[r][c + 0] = vk.x; Ks[r][c + 1] = vk.y;
            Ks[r][c + 2] = vk.z; Ks[r][c + 3] = vk.w;
            float4 vv = *(const float4*)(vb + (size_t)(kt * 32 + r) * DD + c);
            Vs[r][c + 0] = vv.x; Vs[r][c + 1] = vv.y;
            Vs[r][c + 2] = vv.z; Vs[r][c + 3] = vv.w;
        }
        __syncthreads();

        // scores: 4x2 per thread, dot over 64
        float sc[4][2];
#pragma unroll
        for (int i = 0; i < 4; ++i) { sc[i][0] = 0.f; sc[i][1] = 0.f; }
#pragma unroll
        for (int kk = 0; kk < 64; ++kk) {
            float qv[4], kv[2];
#pragma unroll
            for (int i = 0; i < 4; ++i) qv[i] = Qs[tq0 + i][kk];
            kv[0] = Ks[tk0][kk]; kv[1] = Ks[tk0 + 1][kk];
#pragma unroll
            for (int i = 0; i < 4; ++i) {
                sc[i][0] = fmaf(qv[i], kv[0], sc[i][0]);
                sc[i][1] = fmaf(qv[i], kv[1], sc[i][1]);
            }
        }
#pragma unroll
        for (int i = 0; i < 4; ++i)
#pragma unroll
            for (int j = 0; j < 2; ++j) {
                const int qg = q0 + tq0 + i;
                const int kg = kt * 32 + tk0 + j;
                float sval = sc[i][j] * 0.125f;
                if (kg > qg) sval = -1.0e30f;
                Ps[tq0 + i][tk0 + j] = sval;
            }
        __syncthreads();

        // online softmax row stats (one thread per query row)
        if (tid < 64) {
            const float m_old = m_s[tid];
            float mx = m_old;
#pragma unroll
            for (int c = 0; c < 32; ++c) mx = fmaxf(mx, Ps[tid][c]);
            const float alpha = expf(m_old - mx);
            float sum = 0.f;
#pragma unroll
            for (int c = 0; c < 32; ++c) {
                const float p = expf(Ps[tid][c] - mx);
                Ps[tid][c] = p;
                sum += p;
            }
            m_s[tid] = mx;
            l_s[tid] = l_s[tid] * alpha + sum;
            a_s[tid] = alpha;
        }
        __syncthreads();

        // rescale + accumulate O += P @ V
#pragma unroll
        for (int i = 0; i < 4; ++i) {
            const float a = a_s[tq0 + i];
#pragma unroll
            for (int j = 0; j < 4; ++j) oacc[i][j] *= a;
        }
#pragma unroll
        for (int kk = 0; kk < 32; ++kk) {
            float pv[4];
#pragma unroll
            for (int i = 0; i < 4; ++i) pv[i] = Ps[tq0 + i][kk];
            float vv[4];
#pragma unroll
            for (int j = 0; j < 4; ++j) vv[j] = Vs[kk][tc0 + j];
#pragma unroll
            for (int i = 0; i < 4; ++i)
#pragma unroll
                for (int j = 0; j < 4; ++j)
                    oacc[i][j] = fmaf(pv[i], vv[j], oacc[i][j]);
        }
    }

    // write out
#pragma unroll
    for (int i = 0; i < 4; ++i) {
        const float inv = 1.0f / l_s[tq0 + i];
        const size_t roff = (size_t)(q0 + tq0 + i) * DD + tc0;
#pragma unroll
        for (int j = 0; j < 4; ++j) ob[roff + j] = oacc[i][j] * inv;
    }
}

// ---------------- host launcher ---------------------------------------------
extern "C" void kernel_launch(void* const* d_in, const int* in_sizes, int n_in,
                              void* d_out, int out_size) {
    const float* x     = (const float*)d_in[0];
    const float* ln1_g = (const float*)d_in[1];
    const float* ln1_b = (const float*)d_in[2];
    const float* wq    = (const float*)d_in[3];
    const float* bq    = (const float*)d_in[4];
    const float* wk    = (const float*)d_in[5];
    const float* bk    = (const float*)d_in[6];
    const float* wv    = (const float*)d_in[7];
    const float* bv    = (const float*)d_in[8];
    const float* wo    = (const float*)d_in[9];
    const float* bo    = (const float*)d_in[10];
    const float* ln2_g = (const float*)d_in[11];
    const float* ln2_b = (const float*)d_in[12];
    const float* w1    = (const float*)d_in[13];
    const float* b1    = (const float*)d_in[14];
    const float* w2    = (const float*)d_in[15];
    const float* b2    = (const float*)d_in[16];
    float* out = (float*)d_out;

    float *p_h, *p_q, *p_k, *p_v, *p_o, *p_add1, *p_h2, *p_act;
    cudaGetSymbolAddress((void**)&p_h,    g_h);
    cudaGetSymbolAddress((void**)&p_q,    g_q);
    cudaGetSymbolAddress((void**)&p_k,    g_k);
    cudaGetSymbolAddress((void**)&p_v,    g_v);
    cudaGetSymbolAddress((void**)&p_o,    g_o);
    cudaGetSymbolAddress((void**)&p_add1, g_add1);
    cudaGetSymbolAddress((void**)&p_h2,   g_h2);
    cudaGetSymbolAddress((void**)&p_act,  g_act);

    // 1) ln1
    ln_kernel<<<NTOK, 256>>>(x, ln1_g, ln1_b, p_h);

    // 2) q,k,v projections
    {
        dim3 grid(DD / 128, NTOK / 128);
        sgemm_kernel<false, false><<<grid, 256>>>(p_h, wq, bq, nullptr, p_q, NTOK, DD, DD);
        sgemm_kernel<false, false><<<grid, 256>>>(p_h, wk, bk, nullptr, p_k, NTOK, DD, DD);
        sgemm_kernel<false, false><<<grid, 256>>>(p_h, wv, bv, nullptr, p_v, NTOK, DD, DD);
    }

    // 3) causal attention
    {
        dim3 grid(SS / 64, BB * HH);
        attn_kernel<<<grid, 256>>>(p_q, p_k, p_v, p_o);
    }

    // 4) O projection + residual: add1 = x + (o @ wo + bo)
    {
        dim3 grid(DD / 128, NTOK / 128);
        sgemm_kernel<true, false><<<grid, 256>>>(p_o, wo, bo, x, p_add1, NTOK, DD, DD);
    }

    // 5) ln2
    ln_kernel<<<NTOK, 256>>>(p_add1, ln2_g, ln2_b, p_h2);

    // 6) mlp up + gelu
    {
        dim3 grid(FF / 128, NTOK / 128);
        sgemm_kernel<false, true><<<grid, 256>>>(p_h2, w1, b1, nullptr, p_act, NTOK, FF, DD);
    }

    // 7) mlp down + residual: out = add1 + (act @ w2 + b2)
    {
        dim3 grid(DD / 128, NTOK / 128);
        sgemm_kernel<true, false><<<grid, 256>>>(p_act, w2, b2, p_add1, out, NTOK, DD, FF);
    }
}

// round 3
// speedup vs baseline: 1.7426x; 1.7426x over previous
#include <cuda_runtime.h>
#include <cuda_bf16.h>
#include <math.h>
#include <stdint.h>

// Problem dims (fixed)
#define BB 2
#define SS 2048
#define DD 1024
#define HH 16
#define DHH 64
#define FF 4096
#define NTOK (BB*SS)   // 4096

// ---------------- scratch (device globals) -----------------------------------
__device__ __nv_bfloat16 g_h_hi [NTOK*DD], g_h_lo [NTOK*DD];
__device__ float         g_q[NTOK*DD], g_k[NTOK*DD], g_v[NTOK*DD];
__device__ __nv_bfloat16 g_o_hi [NTOK*DD], g_o_lo [NTOK*DD];
__device__ float         g_add1[NTOK*DD];
__device__ __nv_bfloat16 g_h2_hi[NTOK*DD], g_h2_lo[NTOK*DD];
__device__ __nv_bfloat16 g_act_hi[NTOK*FF], g_act_lo[NTOK*FF];
__device__ __nv_bfloat16 g_wq_hi[DD*DD], g_wq_lo[DD*DD];
__device__ __nv_bfloat16 g_wk_hi[DD*DD], g_wk_lo[DD*DD];
__device__ __nv_bfloat16 g_wv_hi[DD*DD], g_wv_lo[DD*DD];
__device__ __nv_bfloat16 g_wo_hi[DD*DD], g_wo_lo[DD*DD];
__device__ __nv_bfloat16 g_w1_hi[DD*FF], g_w1_lo[DD*FF];
__device__ __nv_bfloat16 g_w2_hi[FF*DD], g_w2_lo[FF*DD];

// ---------------- helpers ------------------------------------------------------
__device__ __forceinline__ uint32_t smem_u32(const void* p) {
    uint32_t a;
    asm("{ .reg .u64 t; cvta.to.shared.u64 t, %1; cvt.u32.u64 %0, t; }" : "=r"(a) : "l"(p));
    return a;
}

__device__ __forceinline__ void cp_async16(uint32_t dst, const void* src) {
    asm volatile("cp.async.cg.shared.global [%0], [%1], 16;"
                 :: "r"(dst), "l"(src) : "memory");
}
__device__ __forceinline__ void cp_commit() {
    asm volatile("cp.async.commit_group;" ::: "memory");
}
template<int N>
__device__ __forceinline__ void cp_wait() {
    asm volatile("cp.async.wait_group %0;" :: "n"(N) : "memory");
}

__device__ __forceinline__ void ldsm_x4(uint32_t* r, uint32_t addr) {
    asm volatile("ldmatrix.sync.aligned.m8n8.x4.shared.b16 {%0,%1,%2,%3}, [%4];"
                 : "=r"(r[0]), "=r"(r[1]), "=r"(r[2]), "=r"(r[3]) : "r"(addr));
}

__device__ __forceinline__ void mma16816(float* d, const uint32_t* a, const uint32_t* b) {
    asm volatile(
        "mma.sync.aligned.m16n8k16.row.col.f32.bf16.bf16.f32 "
        "{%0,%1,%2,%3}, {%4,%5,%6,%7}, {%8,%9}, {%0,%1,%2,%3};"
        : "+f"(d[0]), "+f"(d[1]), "+f"(d[2]), "+f"(d[3])
        : "r"(a[0]), "r"(a[1]), "r"(a[2]), "r"(a[3]), "r"(b[0]), "r"(b[1]));
}

// ---------------- LayerNorm -> bf16 hi/lo split --------------------------------
__global__ void ln_split_kernel(const float* __restrict__ x,
                                const float* __restrict__ g,
                                const float* __restrict__ b,
                                __nv_bfloat16* __restrict__ yhi,
                                __nv_bfloat16* __restrict__ ylo) {
    const int row = blockIdx.x;
    const int tid = threadIdx.x;   // 256
    const float* xr = x + (size_t)row * DD;

    float v[4];
    float s = 0.f, s2 = 0.f;
#pragma unroll
    for (int i = 0; i < 4; ++i) {
        v[i] = xr[tid + i * 256];
        s += v[i]; s2 += v[i] * v[i];
    }
    for (int off = 16; off > 0; off >>= 1) {
        s  += __shfl_down_sync(0xffffffffu, s,  off);
        s2 += __shfl_down_sync(0xffffffffu, s2, off);
    }
    __shared__ float rs[8], rs2[8];
    if ((tid & 31) == 0) { rs[tid >> 5] = s; rs2[tid >> 5] = s2; }
    __syncthreads();
    if (tid < 8) { s = rs[tid]; s2 = rs2[tid]; } else { s = 0.f; s2 = 0.f; }
    if (tid < 32) {
        for (int off = 4; off > 0; off >>= 1) {
            s  += __shfl_down_sync(0xffffffffu, s,  off);
            s2 += __shfl_down_sync(0xffffffffu, s2, off);
        }
        if (tid == 0) { rs[0] = s; rs2[0] = s2; }
    }
    __syncthreads();
    const float mean = rs[0] * (1.0f / DD);
    const float var  = rs2[0] * (1.0f / DD) - mean * mean;
    const float inv  = rsqrtf(var + 1e-5f);
    __nv_bfloat16* yh = yhi + (size_t)row * DD;
    __nv_bfloat16* yl = ylo + (size_t)row * DD;
#pragma unroll
    for (int i = 0; i < 4; ++i) {
        const int c = tid + i * 256;
        float o = (v[i] - mean) * inv * g[c] + b[c];
        __nv_bfloat16 h = __float2bfloat16(o);
        yh[c] = h;
        yl[c] = __float2bfloat16(o - __bfloat162float(h));
    }
}

// ---------------- weight transpose + split: w[K,N] fp32 -> [N,K] bf16 hi/lo ----
__global__ void wsplit_kernel(const float* __restrict__ w,
                              __nv_bfloat16* __restrict__ bhi,
                              __nv_bfloat16* __restrict__ blo, int K, int N) {
    __shared__ float t[32][33];
    const int bx = blockIdx.x;   // n tile
    const int by = blockIdx.y;   // k tile
    const int tx = threadIdx.x & 31;
    const int ty = threadIdx.x >> 5;   // 0..7
#pragma unroll
    for (int i = 0; i < 32; i += 8)
        t[ty + i][tx] = w[(size_t)(by * 32 + ty + i) * N + bx * 32 + tx];
    __syncthreads();
#pragma unroll
    for (int i = 0; i < 32; i += 8) {
        const int n = bx * 32 + ty + i;
        const int k = by * 32 + tx;
        float v = t[tx][ty + i];
        __nv_bfloat16 h = __float2bfloat16(v);
        bhi[(size_t)n * K + k] = h;
        blo[(size_t)n * K + k] = __float2bfloat16(v - __bfloat162float(h));
    }
}

// ---------------- mma.sync GEMM: C[M,N] = A[M,K] @ B^T ([N,K] stored) ---------
// bf16x3: C = Ahi*Bhi + Alo*Bhi + Ahi*Blo, fp32 accumulate.
// CTA tile 128x128, BK=32, 256 threads (8 warps, 4x2), warp tile 32x64.
// SMEM rows padded to 40 bf16 (80 B = 20 banks) -> conflict-free ldmatrix.
#define ROWE 40
#define ROWB 80
#define TILESZ (128*ROWB)         // 10240 B
#define BUFSZ  (4*TILESZ)         // Ahi,Alo,Bhi,Blo = 40960 B
#define GEMM_SMEM (2*BUFSZ + 512)

__device__ __forceinline__ void issue_chunk(const __nv_bfloat16* const* tp, int k0,
                                            uint32_t buf, int tid, int K) {
#pragma unroll
    for (int t = 0; t < 4; ++t) {
#pragma unroll
        for (int u = 0; u < 2; ++u) {
            const int lin = tid + u * 256;       // 0..511
            const int r = lin >> 2;              // 0..127
            const int c4 = lin & 3;              // 16B chunk
            const void* src = tp[t] + (size_t)r * K + k0 + c4 * 8;
            cp_async16(buf + t * TILESZ + r * ROWB + c4 * 16, src);
        }
    }
    cp_commit();
}

template<int OUTMODE /*0=f32, 1=bf16 pair*/, bool HAS_RES, bool DO_GELU>
__global__ void __launch_bounds__(256)
tc_gemm(const __nv_bfloat16* __restrict__ Ahi, const __nv_bfloat16* __restrict__ Alo,
        const __nv_bfloat16* __restrict__ Bhi, const __nv_bfloat16* __restrict__ Blo,
        const float* __restrict__ bias, const float* __restrict__ res,
        float* __restrict__ Cf,
        __nv_bfloat16* __restrict__ Chi, __nv_bfloat16* __restrict__ Clo,
        int M, int N, int K) {
    extern __shared__ char smem[];
    const uint32_t sbase = smem_u32(smem);
    float* bias_s = (float*)(smem + 2 * BUFSZ);

    const int tid  = threadIdx.x;
    const int wid  = tid >> 5;
    const int lane = tid & 31;
    const int wm = wid >> 1;        // 0..3
    const int wn = wid & 1;         // 0..1
    const int bx = blockIdx.x, by = blockIdx.y;

    if (tid < 128) bias_s[tid] = bias[bx * 128 + tid];

    const size_t aoff = (size_t)by * 128 * K;
    const size_t boff = (size_t)bx * 128 * K;
    const __nv_bfloat16* tp[4] = { Ahi + aoff, Alo + aoff, Bhi + boff, Blo + boff };

    const int nchunk = K >> 5;

    float acc[2][8][4];
#pragma unroll
    for (int mt = 0; mt < 2; ++mt)
#pragma unroll
        for (int nt = 0; nt < 8; ++nt)
#pragma unroll
            for (int e = 0; e < 4; ++e) acc[mt][nt][e] = 0.f;

    // ldmatrix base offsets (per-thread, within a tile)
    const int a_row = wm * 32 + (lane & 15);
    const int a_kof = (lane >> 4) << 3;
    const int b_row = wn * 64 + (lane & 7) + ((lane >> 4) << 3);
    const int b_kof = ((lane >> 3) & 1) << 3;

    issue_chunk(tp, 0, sbase, tid, K);

    for (int i = 0; i < nchunk; ++i) {
        if (i + 1 < nchunk)
            issue_chunk(tp, (i + 1) << 5, sbase + ((i + 1) & 1) * BUFSZ, tid, K);
        if (i + 1 < nchunk) cp_wait<1>(); else cp_wait<0>();
        __syncthreads();

        const uint32_t buf = sbase + (i & 1) * BUFSZ;
        const uint32_t aAh = buf + a_row * ROWB;
        const uint32_t aAl = aAh + TILESZ;
        const uint32_t aBh = buf + 2 * TILESZ + b_row * ROWB;
        const uint32_t aBl = aBh + TILESZ;

#pragma unroll
        for (int ks = 0; ks < 2; ++ks) {
            const int ak = (ks * 16 + a_kof) * 2;
            const int bk = (ks * 16 + b_kof) * 2;
            uint32_t ah[2][4], al[2][4], bh[8][2], bl[8][2];
#pragma unroll
            for (int mt = 0; mt < 2; ++mt) {
                ldsm_x4(ah[mt], aAh + mt * 16 * ROWB + ak);
                ldsm_x4(al[mt], aAl + mt * 16 * ROWB + ak);
            }
#pragma unroll
            for (int p = 0; p < 4; ++p) {
                uint32_t r[4];
                ldsm_x4(r, aBh + p * 16 * ROWB + bk);
                bh[2*p][0] = r[0]; bh[2*p][1] = r[1];
                bh[2*p+1][0] = r[2]; bh[2*p+1][1] = r[3];
                ldsm_x4(r, aBl + p * 16 * ROWB + bk);
                bl[2*p][0] = r[0]; bl[2*p][1] = r[1];
                bl[2*p+1][0] = r[2]; bl[2*p+1][1] = r[3];
            }
#pragma unroll
            for (int mt = 0; mt < 2; ++mt)
#pragma unroll
                for (int nt = 0; nt < 8; ++nt) {
                    mma16816(acc[mt][nt], ah[mt], bh[nt]);
                    mma16816(acc[mt][nt], al[mt], bh[nt]);
                    mma16816(acc[mt][nt], ah[mt], bl[nt]);
                }
        }
        __syncthreads();
    }

    // ---------------- epilogue ----------------
    const int mbase = by * 128 + wm * 32;
    const int nloc0 = wn * 64;
#pragma unroll
    for (int mt = 0; mt < 2; ++mt) {
#pragma unroll
        for (int half = 0; half < 2; ++half) {
            const int m = mbase + mt * 16 + (lane >> 2) + half * 8;
#pragma unroll
            for (int nt = 0; nt < 8; ++nt) {
                const int nloc = nloc0 + nt * 8 + 2 * (lane & 3);
                const int n = bx * 128 + nloc;
                float v0 = acc[mt][nt][half * 2 + 0] + bias_s[nloc];
                float v1 = acc[mt][nt][half * 2 + 1] + bias_s[nloc + 1];
                if (DO_GELU) {
                    v0 = 0.5f * v0 * (1.0f + erff(v0 * 0.70710678118654752f));
                    v1 = 0.5f * v1 * (1.0f + erff(v1 * 0.70710678118654752f));
                }
                if (HAS_RES) {
                    const float2 rv = *(const float2*)(res + (size_t)m * N + n);
                    v0 += rv.x; v1 += rv.y;
                }
                if (OUTMODE == 0) {
                    *(float2*)(Cf + (size_t)m * N + n) = make_float2(v0, v1);
                } else {
                    __nv_bfloat16 h0 = __float2bfloat16(v0);
                    __nv_bfloat16 h1 = __float2bfloat16(v1);
                    __nv_bfloat16 l0 = __float2bfloat16(v0 - __bfloat162float(h0));
                    __nv_bfloat16 l1 = __float2bfloat16(v1 - __bfloat162float(h1));
                    *(__nv_bfloat162*)(Chi + (size_t)m * N + n) = __halves2bfloat162(h0, h1);
                    *(__nv_bfloat162*)(Clo + (size_t)m * N + n) = __halves2bfloat162(l0, l1);
                }
            }
        }
    }
}

// ---------------- Flash attention (fp32, causal), writes bf16 hi/lo ------------
__global__ void __launch_bounds__(256)
attn_kernel(const float* __restrict__ q, const float* __restrict__ k,
            const float* __restrict__ v,
            __nv_bfloat16* __restrict__ o_hi, __nv_bfloat16* __restrict__ o_lo) {
    const int qt = blockIdx.x;
    const int bh = blockIdx.y;
    const int b = bh / HH, h = bh % HH;
    const size_t base = (size_t)b * SS * DD + (size_t)h * DHH;
    const float* qb = q + base;
    const float* kb = k + base;
    const float* vb = v + base;

    __shared__ float Qs[64][65];
    __shared__ float Ks[32][65];
    __shared__ float Vs[32][65];
    __shared__ float Ps[64][33];
    __shared__ float m_s[64], l_s[64], a_s[64];

    const int tid = threadIdx.x;
    const int q0 = qt * 64;

#pragma unroll
    for (int i = 0; i < 4; ++i) {
        const int lin = tid + i * 256;
        const int r = lin >> 4, c = (lin & 15) * 4;
        float4 vq = *(const float4*)(qb + (size_t)(q0 + r) * DD + c);
        Qs[r][c+0] = vq.x; Qs[r][c+1] = vq.y; Qs[r][c+2] = vq.z; Qs[r][c+3] = vq.w;
    }
    if (tid < 64) { m_s[tid] = -3.0e38f; l_s[tid] = 0.f; }

    const int tq0 = (tid >> 4) * 4;
    const int tk0 = (tid & 15) * 2;
    const int tc0 = (tid & 15) * 4;

    float oacc[4][4];
#pragma unroll
    for (int i = 0; i < 4; ++i)
#pragma unroll
        for (int j = 0; j < 4; ++j) oacc[i][j] = 0.f;

    const int ntiles = qt * 2 + 2;
    for (int kt = 0; kt < ntiles; ++kt) {
        __syncthreads();
#pragma unroll
        for (int i = 0; i < 2; ++i) {
            const int lin = tid + i * 256;
            const int r = lin >> 4, c = (lin & 15) * 4;
            float4 vk = *(const float4*)(kb + (size_t)(kt * 32 + r) * DD + c);
            Ks[r][c+0] = vk.x; Ks[r][c+1] = vk.y; Ks[r][c+2] = vk.z; Ks[r][c+3] = vk.w;
            float4 vv = *(const float4*)(vb + (size_t)(kt * 32 + r) * DD + c);
            Vs[r][c+0] = vv.x; Vs[r][c+1] = vv.y; Vs[r][c+2] = vv.z; Vs[r][c+3] = vv.w;
        }
        __syncthreads();

        float sc[4][2];
#pragma unroll
        for (int i = 0; i < 4; ++i) { sc[i][0] = 0.f; sc[i][1] = 0.f; }
#pragma unroll
        for (int kk = 0; kk < 64; ++kk) {
            float qv[4], kv[2];
#pragma unroll
            for (int i = 0; i < 4; ++i) qv[i] = Qs[tq0 + i][kk];
            kv[0] = Ks[tk0][kk]; kv[1] = Ks[tk0 + 1][kk];
#pragma unroll
            for (int i = 0; i < 4; ++i) {
                sc[i][0] = fmaf(qv[i], kv[0], sc[i][0]);
                sc[i][1] = fmaf(qv[i], kv[1], sc[i][1]);
            }
        }
#pragma unroll
        for (int i = 0; i < 4; ++i)
#pragma unroll
            for (int j = 0; j < 2; ++j) {
                const int qg = q0 + tq0 + i;
                const int kg = kt * 32 + tk0 + j;
                float sval = sc[i][j] * 0.125f;
                if (kg > qg) sval = -1.0e30f;
                Ps[tq0 + i][tk0 + j] = sval;
            }
        __syncthreads();

        if (tid < 64) {
            const float m_old = m_s[tid];
            float mx = m_old;
#pragma unroll
            for (int c = 0; c < 32; ++c) mx = fmaxf(mx, Ps[tid][c]);
            const float alpha = expf(m_old - mx);
            float sum = 0.f;
#pragma unroll
            for (int c = 0; c < 32; ++c) {
                const float p = expf(Ps[tid][c] - mx);
                Ps[tid][c] = p;
                sum += p;
            }
            m_s[tid] = mx;
            l_s[tid] = l_s[tid] * alpha + sum;
            a_s[tid] = alpha;
        }
        __syncthreads();

#pragma unroll
        for (int i = 0; i < 4; ++i) {
            const float a = a_s[tq0 + i];
#pragma unroll
            for (int j = 0; j < 4; ++j) oacc[i][j] *= a;
        }
#pragma unroll
        for (int kk = 0; kk < 32; ++kk) {
            float pv[4];
#pragma unroll
            for (int i = 0; i < 4; ++i) pv[i] = Ps[tq0 + i][kk];
            float vvv[4];
#pragma unroll
            for (int j = 0; j < 4; ++j) vvv[j] = Vs[kk][tc0 + j];
#pragma unroll
            for (int i = 0; i < 4; ++i)
#pragma unroll
                for (int j = 0; j < 4; ++j)
                    oacc[i][j] = fmaf(pv[i], vvv[j], oacc[i][j]);
        }
    }

    __nv_bfloat16* obh = o_hi + base;
    __nv_bfloat16* obl = o_lo + base;
#pragma unroll
    for (int i = 0; i < 4; ++i) {
        const float inv = 1.0f / l_s[tq0 + i];
        const size_t roff = (size_t)(q0 + tq0 + i) * DD + tc0;
#pragma unroll
        for (int j = 0; j < 4; ++j) {
            float val = oacc[i][j] * inv;
            __nv_bfloat16 hh = __float2bfloat16(val);
            obh[roff + j] = hh;
            obl[roff + j] = __float2bfloat16(val - __bfloat162float(hh));
        }
    }
}

// ---------------- host launcher -------------------------------------------------
extern "C" void kernel_launch(void* const* d_in, const int* in_sizes, int n_in,
                              void* d_out, int out_size) {
    const float* x     = (const float*)d_in[0];
    const float* ln1_g = (const float*)d_in[1];
    const float* ln1_b = (const float*)d_in[2];
    const float* wq    = (const float*)d_in[3];
    const float* bq    = (const float*)d_in[4];
    const float* wk    = (const float*)d_in[5];
    const float* bk    = (const float*)d_in[6];
    const float* wv    = (const float*)d_in[7];
    const float* bv    = (const float*)d_in[8];
    const float* wo    = (const float*)d_in[9];
    const float* bo    = (const float*)d_in[10];
    const float* ln2_g = (const float*)d_in[11];
    const float* ln2_b = (const float*)d_in[12];
    const float* w1    = (const float*)d_in[13];
    const float* b1    = (const float*)d_in[14];
    const float* w2    = (const float*)d_in[15];
    const float* b2    = (const float*)d_in[16];
    float* out = (float*)d_out;

    __nv_bfloat16 *hhi, *hlo, *ohi, *olo, *h2hi, *h2lo, *acthi, *actlo;
    __nv_bfloat16 *wqh, *wql, *wkh, *wkl, *wvh, *wvl, *woh, *wol, *w1h, *w1l, *w2h, *w2l;
    float *pq, *pk, *pv, *padd1;
    cudaGetSymbolAddress((void**)&hhi,  g_h_hi);  cudaGetSymbolAddress((void**)&hlo,  g_h_lo);
    cudaGetSymbolAddress((void**)&pq,   g_q);     cudaGetSymbolAddress((void**)&pk,   g_k);
    cudaGetSymbolAddress((void**)&pv,   g_v);
    cudaGetSymbolAddress((void**)&ohi,  g_o_hi);  cudaGetSymbolAddress((void**)&olo,  g_o_lo);
    cudaGetSymbolAddress((void**)&padd1,g_add1);
    cudaGetSymbolAddress((void**)&h2hi, g_h2_hi); cudaGetSymbolAddress((void**)&h2lo, g_h2_lo);
    cudaGetSymbolAddress((void**)&acthi,g_act_hi);cudaGetSymbolAddress((void**)&actlo,g_act_lo);
    cudaGetSymbolAddress((void**)&wqh,  g_wq_hi); cudaGetSymbolAddress((void**)&wql,  g_wq_lo);
    cudaGetSymbolAddress((void**)&wkh,  g_wk_hi); cudaGetSymbolAddress((void**)&wkl,  g_wk_lo);
    cudaGetSymbolAddress((void**)&wvh,  g_wv_hi); cudaGetSymbolAddress((void**)&wvl,  g_wv_lo);
    cudaGetSymbolAddress((void**)&woh,  g_wo_hi); cudaGetSymbolAddress((void**)&wol,  g_wo_lo);
    cudaGetSymbolAddress((void**)&w1h,  g_w1_hi); cudaGetSymbolAddress((void**)&w1l,  g_w1_lo);
    cudaGetSymbolAddress((void**)&w2h,  g_w2_hi); cudaGetSymbolAddress((void**)&w2l,  g_w2_lo);

    cudaFuncSetAttribute(tc_gemm<0,false,false>, cudaFuncAttributeMaxDynamicSharedMemorySize, GEMM_SMEM);
    cudaFuncSetAttribute(tc_gemm<0,true, false>, cudaFuncAttributeMaxDynamicSharedMemorySize, GEMM_SMEM);
    cudaFuncSetAttribute(tc_gemm<1,false,true >, cudaFuncAttributeMaxDynamicSharedMemorySize, GEMM_SMEM);

    // weight transpose + bf16 split
    wsplit_kernel<<<dim3(DD/32, DD/32), 256>>>(wq, wqh, wql, DD, DD);
    wsplit_kernel<<<dim3(DD/32, DD/32), 256>>>(wk, wkh, wkl, DD, DD);
    wsplit_kernel<<<dim3(DD/32, DD/32), 256>>>(wv, wvh, wvl, DD, DD);
    wsplit_kernel<<<dim3(DD/32, DD/32), 256>>>(wo, woh, wol, DD, DD);
    wsplit_kernel<<<dim3(FF/32, DD/32), 256>>>(w1, w1h, w1l, DD, FF);
    wsplit_kernel<<<dim3(DD/32, FF/32), 256>>>(w2, w2h, w2l, FF, DD);

    // ln1 -> bf16 split
    ln_split_kernel<<<NTOK, 256>>>(x, ln1_g, ln1_b, hhi, hlo);

    // QKV projections (fp32 out)
    {
        dim3 grid(DD/128, NTOK/128);
        tc_gemm<0,false,false><<<grid, 256, GEMM_SMEM>>>(hhi, hlo, wqh, wql, bq, nullptr, pq, nullptr, nullptr, NTOK, DD, DD);
        tc_gemm<0,false,false><<<grid, 256, GEMM_SMEM>>>(hhi, hlo, wkh, wkl, bk, nullptr, pk, nullptr, nullptr, NTOK, DD, DD);
        tc_gemm<0,false,false><<<grid, 256, GEMM_SMEM>>>(hhi, hlo, wvh, wvl, bv, nullptr, pv, nullptr, nullptr, NTOK, DD, DD);
    }

    // attention
    {
        dim3 grid(SS/64, BB*HH);
        attn_kernel<<<grid, 256>>>(pq, pk, pv, ohi, olo);
    }

    // O-proj + residual: add1 = x + o@wo + bo
    {
        dim3 grid(DD/128, NTOK/128);
        tc_gemm<0,true,false><<<grid, 256, GEMM_SMEM>>>(ohi, olo, woh, wol, bo, x, padd1, nullptr, nullptr, NTOK, DD, DD);
    }

    // ln2 -> bf16 split
    ln_split_kernel<<<NTOK, 256>>>(padd1, ln2_g, ln2_b, h2hi, h2lo);

    // MLP up + gelu -> bf16 pair
    {
        dim3 grid(FF/128, NTOK/128);
        tc_gemm<1,false,true><<<grid, 256, GEMM_SMEM>>>(h2hi, h2lo, w1h, w1l, b1, nullptr, nullptr, acthi, actlo, NTOK, FF, DD);
    }

    // MLP down + residual -> out
    {
        dim3 grid(DD/128, NTOK/128);
        tc_gemm<0,true,false><<<grid, 256, GEMM_SMEM>>>(acthi, actlo, w2h, w2l, b2, padd1, out, nullptr, nullptr, NTOK, DD, FF);
    }
}

// round 4
// speedup vs baseline: 2.4082x; 1.3820x over previous
#include <cuda_runtime.h>
#include <cuda_bf16.h>
#include <math.h>
#include <stdint.h>

// Problem dims (fixed)
#define BB 2
#define SS 2048
#define DD 1024
#define HH 16
#define DHH 64
#define FF 4096
#define NTOK (BB*SS)   // 4096

// ---------------- scratch (device globals) -----------------------------------
__device__ __nv_bfloat16 g_h_hi [NTOK*DD], g_h_lo [NTOK*DD];
__device__ __nv_bfloat16 g_q_hi [NTOK*DD], g_q_lo [NTOK*DD];
__device__ __nv_bfloat16 g_k_hi [NTOK*DD], g_k_lo [NTOK*DD];
__device__ __nv_bfloat16 g_v_hi [NTOK*DD], g_v_lo [NTOK*DD];
__device__ __nv_bfloat16 g_o_hi [NTOK*DD], g_o_lo [NTOK*DD];
__device__ float         g_add1[NTOK*DD];
__device__ __nv_bfloat16 g_h2_hi[NTOK*DD], g_h2_lo[NTOK*DD];
__device__ __nv_bfloat16 g_act_hi[NTOK*FF], g_act_lo[NTOK*FF];
__device__ __nv_bfloat16 g_wq_hi[DD*DD], g_wq_lo[DD*DD];
__device__ __nv_bfloat16 g_wk_hi[DD*DD], g_wk_lo[DD*DD];
__device__ __nv_bfloat16 g_wv_hi[DD*DD], g_wv_lo[DD*DD];
__device__ __nv_bfloat16 g_wo_hi[DD*DD], g_wo_lo[DD*DD];
__device__ __nv_bfloat16 g_w1_hi[DD*FF], g_w1_lo[DD*FF];
__device__ __nv_bfloat16 g_w2_hi[FF*DD], g_w2_lo[FF*DD];

// ---------------- helpers ------------------------------------------------------
__device__ __forceinline__ uint32_t smem_u32(const void* p) {
    uint32_t a;
    asm("{ .reg .u64 t; cvta.to.shared.u64 t, %1; cvt.u32.u64 %0, t; }" : "=r"(a) : "l"(p));
    return a;
}

__device__ __forceinline__ void cp_async16(uint32_t dst, const void* src) {
    asm volatile("cp.async.cg.shared.global [%0], [%1], 16;"
                 :: "r"(dst), "l"(src) : "memory");
}
__device__ __forceinline__ void cp_commit() {
    asm volatile("cp.async.commit_group;" ::: "memory");
}
template<int N>
__device__ __forceinline__ void cp_wait() {
    asm volatile("cp.async.wait_group %0;" :: "n"(N) : "memory");
}

__device__ __forceinline__ void ldsm_x4(uint32_t* r, uint32_t addr) {
    asm volatile("ldmatrix.sync.aligned.m8n8.x4.shared.b16 {%0,%1,%2,%3}, [%4];"
                 : "=r"(r[0]), "=r"(r[1]), "=r"(r[2]), "=r"(r[3]) : "r"(addr));
}
__device__ __forceinline__ void ldsm_x4_t(uint32_t* r, uint32_t addr) {
    asm volatile("ldmatrix.sync.aligned.m8n8.x4.trans.shared.b16 {%0,%1,%2,%3}, [%4];"
                 : "=r"(r[0]), "=r"(r[1]), "=r"(r[2]), "=r"(r[3]) : "r"(addr));
}

__device__ __forceinline__ void mma16816(float* d, const uint32_t* a, const uint32_t* b) {
    asm volatile(
        "mma.sync.aligned.m16n8k16.row.col.f32.bf16.bf16.f32 "
        "{%0,%1,%2,%3}, {%4,%5,%6,%7}, {%8,%9}, {%0,%1,%2,%3};"
        : "+f"(d[0]), "+f"(d[1]), "+f"(d[2]), "+f"(d[3])
        : "r"(a[0]), "r"(a[1]), "r"(a[2]), "r"(a[3]), "r"(b[0]), "r"(b[1]));
}

__device__ __forceinline__ uint32_t packbf(float a, float b) {
    __nv_bfloat162 t = __floats2bfloat162_rn(a, b);
    return *reinterpret_cast<uint32_t*>(&t);
}
__device__ __forceinline__ float bfres(float a) {
    __nv_bfloat16 h = __float2bfloat16(a);
    return a - __bfloat162float(h);
}

// ---------------- LayerNorm -> bf16 hi/lo split --------------------------------
__global__ void ln_split_kernel(const float* __restrict__ x,
                                const float* __restrict__ g,
                                const float* __restrict__ b,
                                __nv_bfloat16* __restrict__ yhi,
                                __nv_bfloat16* __restrict__ ylo) {
    const int row = blockIdx.x;
    const int tid = threadIdx.x;   // 256
    const float* xr = x + (size_t)row * DD;

    float v[4];
    float s = 0.f, s2 = 0.f;
#pragma unroll
    for (int i = 0; i < 4; ++i) {
        v[i] = xr[tid + i * 256];
        s += v[i]; s2 += v[i] * v[i];
    }
    for (int off = 16; off > 0; off >>= 1) {
        s  += __shfl_down_sync(0xffffffffu, s,  off);
        s2 += __shfl_down_sync(0xffffffffu, s2, off);
    }
    __shared__ float rs[8], rs2[8];
    if ((tid & 31) == 0) { rs[tid >> 5] = s; rs2[tid >> 5] = s2; }
    __syncthreads();
    if (tid < 8) { s = rs[tid]; s2 = rs2[tid]; } else { s = 0.f; s2 = 0.f; }
    if (tid < 32) {
        for (int off = 4; off > 0; off >>= 1) {
            s  += __shfl_down_sync(0xffffffffu, s,  off);
            s2 += __shfl_down_sync(0xffffffffu, s2, off);
        }
        if (tid == 0) { rs[0] = s; rs2[0] = s2; }
    }
    __syncthreads();
    const float mean = rs[0] * (1.0f / DD);
    const float var  = rs2[0] * (1.0f / DD) - mean * mean;
    const float inv  = rsqrtf(var + 1e-5f);
    __nv_bfloat16* yh = yhi + (size_t)row * DD;
    __nv_bfloat16* yl = ylo + (size_t)row * DD;
#pragma unroll
    for (int i = 0; i < 4; ++i) {
        const int c = tid + i * 256;
        float o = (v[i] - mean) * inv * g[c] + b[c];
        __nv_bfloat16 h = __float2bfloat16(o);
        yh[c] = h;
        yl[c] = __float2bfloat16(o - __bfloat162float(h));
    }
}

// ---------------- weight transpose + split: w[K,N] fp32 -> [N,K] bf16 hi/lo ----
__global__ void wsplit_kernel(const float* __restrict__ w,
                              __nv_bfloat16* __restrict__ bhi,
                              __nv_bfloat16* __restrict__ blo, int K, int N) {
    __shared__ float t[32][33];
    const int bx = blockIdx.x;   // n tile
    const int by = blockIdx.y;   // k tile
    const int tx = threadIdx.x & 31;
    const int ty = threadIdx.x >> 5;   // 0..7
#pragma unroll
    for (int i = 0; i < 32; i += 8)
        t[ty + i][tx] = w[(size_t)(by * 32 + ty + i) * N + bx * 32 + tx];
    __syncthreads();
#pragma unroll
    for (int i = 0; i < 32; i += 8) {
        const int n = bx * 32 + ty + i;
        const int k = by * 32 + tx;
        float v = t[tx][ty + i];
        __nv_bfloat16 h = __float2bfloat16(v);
        bhi[(size_t)n * K + k] = h;
        blo[(size_t)n * K + k] = __float2bfloat16(v - __bfloat162float(h));
    }
}

// ---------------- mma.sync GEMM: C[M,N] = A[M,K] @ B^T ([N,K] stored) ---------
#define ROWE 40
#define ROWB 80
#define TILESZ (128*ROWB)
#define BUFSZ  (4*TILESZ)
#define GEMM_SMEM (2*BUFSZ + 512)

__device__ __forceinline__ void issue_chunk(const __nv_bfloat16* const* tp, int k0,
                                            uint32_t buf, int tid, int K) {
#pragma unroll
    for (int t = 0; t < 4; ++t) {
#pragma unroll
        for (int u = 0; u < 2; ++u) {
            const int lin = tid + u * 256;
            const int r = lin >> 2;
            const int c4 = lin & 3;
            const void* src = tp[t] + (size_t)r * K + k0 + c4 * 8;
            cp_async16(buf + t * TILESZ + r * ROWB + c4 * 16, src);
        }
    }
    cp_commit();
}

template<int OUTMODE /*0=f32, 1=bf16 pair*/, bool HAS_RES, bool DO_GELU>
__global__ void __launch_bounds__(256)
tc_gemm(const __nv_bfloat16* __restrict__ Ahi, const __nv_bfloat16* __restrict__ Alo,
        const __nv_bfloat16* __restrict__ Bhi, const __nv_bfloat16* __restrict__ Blo,
        const float* __restrict__ bias, const float* __restrict__ res,
        float* __restrict__ Cf,
        __nv_bfloat16* __restrict__ Chi, __nv_bfloat16* __restrict__ Clo,
        int M, int N, int K) {
    extern __shared__ char smem[];
    const uint32_t sbase = smem_u32(smem);
    float* bias_s = (float*)(smem + 2 * BUFSZ);

    const int tid  = threadIdx.x;
    const int wid  = tid >> 5;
    const int lane = tid & 31;
    const int wm = wid >> 1;
    const int wn = wid & 1;
    const int bx = blockIdx.x, by = blockIdx.y;

    if (tid < 128) bias_s[tid] = bias[bx * 128 + tid];

    const size_t aoff = (size_t)by * 128 * K;
    const size_t boff = (size_t)bx * 128 * K;
    const __nv_bfloat16* tp[4] = { Ahi + aoff, Alo + aoff, Bhi + boff, Blo + boff };

    const int nchunk = K >> 5;

    float acc[2][8][4];
#pragma unroll
    for (int mt = 0; mt < 2; ++mt)
#pragma unroll
        for (int nt = 0; nt < 8; ++nt)
#pragma unroll
            for (int e = 0; e < 4; ++e) acc[mt][nt][e] = 0.f;

    const int a_row = wm * 32 + (lane & 15);
    const int a_kof = (lane >> 4) << 3;
    const int b_row = wn * 64 + (lane & 7) + ((lane >> 4) << 3);
    const int b_kof = ((lane >> 3) & 1) << 3;

    issue_chunk(tp, 0, sbase, tid, K);

    for (int i = 0; i < nchunk; ++i) {
        if (i + 1 < nchunk)
            issue_chunk(tp, (i + 1) << 5, sbase + ((i + 1) & 1) * BUFSZ, tid, K);
        if (i + 1 < nchunk) cp_wait<1>(); else cp_wait<0>();
        __syncthreads();

        const uint32_t buf = sbase + (i & 1) * BUFSZ;
        const uint32_t aAh = buf + a_row * ROWB;
        const uint32_t aAl = aAh + TILESZ;
        const uint32_t aBh = buf + 2 * TILESZ + b_row * ROWB;
        const uint32_t aBl = aBh + TILESZ;

#pragma unroll
        for (int ks = 0; ks < 2; ++ks) {
            const int ak = (ks * 16 + a_kof) * 2;
            const int bk = (ks * 16 + b_kof) * 2;
            uint32_t ah[2][4], al[2][4], bh[8][2], bl[8][2];
#pragma unroll
            for (int mt = 0; mt < 2; ++mt) {
                ldsm_x4(ah[mt], aAh + mt * 16 * ROWB + ak);
                ldsm_x4(al[mt], aAl + mt * 16 * ROWB + ak);
            }
#pragma unroll
            for (int p = 0; p < 4; ++p) {
                uint32_t r[4];
                ldsm_x4(r, aBh + p * 16 * ROWB + bk);
                bh[2*p][0] = r[0]; bh[2*p][1] = r[1];
                bh[2*p+1][0] = r[2]; bh[2*p+1][1] = r[3];
                ldsm_x4(r, aBl + p * 16 * ROWB + bk);
                bl[2*p][0] = r[0]; bl[2*p][1] = r[1];
                bl[2*p+1][0] = r[2]; bl[2*p+1][1] = r[3];
            }
#pragma unroll
            for (int mt = 0; mt < 2; ++mt)
#pragma unroll
                for (int nt = 0; nt < 8; ++nt) {
                    mma16816(acc[mt][nt], ah[mt], bh[nt]);
                    mma16816(acc[mt][nt], al[mt], bh[nt]);
                    mma16816(acc[mt][nt], ah[mt], bl[nt]);
                }
        }
        __syncthreads();
    }

    const int mbase = by * 128 + wm * 32;
    const int nloc0 = wn * 64;
#pragma unroll
    for (int mt = 0; mt < 2; ++mt) {
#pragma unroll
        for (int half = 0; half < 2; ++half) {
            const int m = mbase + mt * 16 + (lane >> 2) + half * 8;
#pragma unroll
            for (int nt = 0; nt < 8; ++nt) {
                const int nloc = nloc0 + nt * 8 + 2 * (lane & 3);
                const int n = bx * 128 + nloc;
                float v0 = acc[mt][nt][half * 2 + 0] + bias_s[nloc];
                float v1 = acc[mt][nt][half * 2 + 1] + bias_s[nloc + 1];
                if (DO_GELU) {
                    v0 = 0.5f * v0 * (1.0f + erff(v0 * 0.70710678118654752f));
                    v1 = 0.5f * v1 * (1.0f + erff(v1 * 0.70710678118654752f));
                }
                if (HAS_RES) {
                    const float2 rv = *(const float2*)(res + (size_t)m * N + n);
                    v0 += rv.x; v1 += rv.y;
                }
                if (OUTMODE == 0) {
                    *(float2*)(Cf + (size_t)m * N + n) = make_float2(v0, v1);
                } else {
                    __nv_bfloat16 h0 = __float2bfloat16(v0);
                    __nv_bfloat16 h1 = __float2bfloat16(v1);
                    __nv_bfloat16 l0 = __float2bfloat16(v0 - __bfloat162float(h0));
                    __nv_bfloat16 l1 = __float2bfloat16(v1 - __bfloat162float(h1));
                    *(__nv_bfloat162*)(Chi + (size_t)m * N + n) = __halves2bfloat162(h0, h1);
                    *(__nv_bfloat162*)(Clo + (size_t)m * N + n) = __halves2bfloat162(l0, l1);
                }
            }
        }
    }
}

// ---------------- Flash attention via mma.sync (bf16x3, causal) -----------------
// CTA: 128 q-rows x DH=64, 8 warps (16 rows each). K-tiles of 64 keys.
#define AROWB 144   // 72 bf16 per padded row
#define ATT_SMEM (128*AROWB*2 + 64*AROWB*4)   // Q(hi,lo) + K/V(hi,lo) = 73728

__global__ void __launch_bounds__(256, 2)
attn_mma(const __nv_bfloat16* __restrict__ qhi, const __nv_bfloat16* __restrict__ qlo,
         const __nv_bfloat16* __restrict__ khi, const __nv_bfloat16* __restrict__ klo,
         const __nv_bfloat16* __restrict__ vhi, const __nv_bfloat16* __restrict__ vlo,
         __nv_bfloat16* __restrict__ ohi, __nv_bfloat16* __restrict__ olo) {
    extern __shared__ char sm[];
    const uint32_t sb  = smem_u32(sm);
    const uint32_t sQh = sb;
    const uint32_t sQl = sb + 128 * AROWB;
    const uint32_t sKh = sb + 256 * AROWB;
    const uint32_t sKl = sKh + 64 * AROWB;
    const uint32_t sVh = sKl + 64 * AROWB;
    const uint32_t sVl = sVh + 64 * AROWB;

    const int qt = gridDim.x - 1 - blockIdx.x;   // big tiles first
    const int bh = blockIdx.y;
    const int b = bh >> 4, h = bh & 15;
    const size_t base = (size_t)b * SS * DD + (size_t)h * DHH;
    const int q0 = qt * 128;

    const int tid = threadIdx.x, warp = tid >> 5, lane = tid & 31;

    // stage Q (hi/lo)
#pragma unroll
    for (int u = 0; u < 4; ++u) {
        const int lin = tid + u * 256;       // 0..1023
        const int r = lin >> 3, c = lin & 7;
        const size_t go = base + (size_t)(q0 + r) * DD + c * 8;
        cp_async16(sQh + r * AROWB + c * 16, qhi + go);
        cp_async16(sQl + r * AROWB + c * 16, qlo + go);
    }
    cp_commit();

    float sfr[8][4], oac[8][4];
    float m0 = -1e30f, m1 = -1e30f, l0 = 0.f, l1 = 0.f;
#pragma unroll
    for (int j = 0; j < 8; ++j)
#pragma unroll
        for (int e = 0; e < 4; ++e) oac[j][e] = 0.f;

    const uint32_t qbh = sQh + (warp * 16 + (lane & 15)) * AROWB + (((lane >> 4) << 3) << 1);
    const uint32_t qbl = qbh + 128 * AROWB;
    const int krow = (lane & 7) + ((lane >> 4) << 3);
    const uint32_t kof = (((lane >> 3) & 1) << 3) << 1;
    const int vrow = lane & 15;
    const uint32_t vof = (((lane >> 4) << 3)) << 1;

    cp_wait<0>();
    __syncthreads();

    const int ntile = qt * 2 + 2;
    for (int kt = 0; kt < ntile; ++kt) {
        const int k0 = kt * 64;
        __syncthreads();   // previous tile fully consumed
        {
            const __nv_bfloat16* src0 = khi + base + (size_t)k0 * DD;
            const __nv_bfloat16* src1 = klo + base + (size_t)k0 * DD;
            const __nv_bfloat16* src2 = vhi + base + (size_t)k0 * DD;
            const __nv_bfloat16* src3 = vlo + base + (size_t)k0 * DD;
#pragma unroll
            for (int u = 0; u < 2; ++u) {
                const int lin = tid + u * 256;   // 0..511 -> 64 rows x 8 chunks
                const int rr = lin >> 3, cc = lin & 7;
                const size_t go = (size_t)rr * DD + cc * 8;
                const uint32_t so = rr * AROWB + cc * 16;
                cp_async16(sKh + so, src0 + go);
                cp_async16(sKl + so, src1 + go);
                cp_async16(sVh + so, src2 + go);
                cp_async16(sVl + so, src3 + go);
            }
            cp_commit(); cp_wait<0>();
            __syncthreads();
        }

        // ---- scores: S = Q @ K^T (bf16x3) ----
#pragma unroll
        for (int j = 0; j < 8; ++j)
#pragma unroll
            for (int e = 0; e < 4; ++e) sfr[j][e] = 0.f;
#pragma unroll
        for (int t = 0; t < 4; ++t) {
            uint32_t qah[4], qal[4];
            ldsm_x4(qah, qbh + t * 32);
            ldsm_x4(qal, qbl + t * 32);
#pragma unroll
            for (int g = 0; g < 4; ++g) {
                uint32_t kbh[4], kbl[4];
                const uint32_t ka = (g * 16 + krow) * AROWB + t * 32 + kof;
                ldsm_x4(kbh, sKh + ka);
                ldsm_x4(kbl, sKl + ka);
                mma16816(sfr[2*g],   qah, kbh);
                mma16816(sfr[2*g],   qal, kbh);
                mma16816(sfr[2*g],   qah, kbl);
                mma16816(sfr[2*g+1], qah, kbh + 2);
                mma16816(sfr[2*g+1], qal, kbh + 2);
                mma16816(sfr[2*g+1], qah, kbl + 2);
            }
        }

        // ---- online softmax (base-2 domain, warp-local rows) ----
        const float cs = 0.1803368801111204f;   // 0.125 * log2(e)
        const int rg0 = q0 + warp * 16 + (lane >> 2);
        if (kt >= 2 * qt) {  // diagonal tiles need masking
#pragma unroll
            for (int j = 0; j < 8; ++j) {
                const int cb = k0 + j * 8 + 2 * (lane & 3);
#pragma unroll
                for (int e = 0; e < 4; ++e) {
                    const int cg = cb + (e & 1);
                    const int rg = rg0 + ((e >> 1) << 3);
                    const float s = sfr[j][e] * cs;
                    sfr[j][e] = (cg > rg) ? -1e30f : s;
                }
            }
        } else {
#pragma unroll
            for (int j = 0; j < 8; ++j)
#pragma unroll
                for (int e = 0; e < 4; ++e) sfr[j][e] *= cs;
        }
        float mx0 = -1e30f, mx1 = -1e30f;
#pragma unroll
        for (int j = 0; j < 8; ++j) {
            mx0 = fmaxf(mx0, fmaxf(sfr[j][0], sfr[j][1]));
            mx1 = fmaxf(mx1, fmaxf(sfr[j][2], sfr[j][3]));
        }
        mx0 = fmaxf(mx0, __shfl_xor_sync(0xffffffffu, mx0, 1));
        mx0 = fmaxf(mx0, __shfl_xor_sync(0xffffffffu, mx0, 2));
        mx1 = fmaxf(mx1, __shfl_xor_sync(0xffffffffu, mx1, 1));
        mx1 = fmaxf(mx1, __shfl_xor_sync(0xffffffffu, mx1, 2));
        mx0 = fmaxf(mx0, m0);
        mx1 = fmaxf(mx1, m1);
        const float al0 = exp2f(m0 - mx0);
        const float al1 = exp2f(m1 - mx1);
        m0 = mx0; m1 = mx1;
        float s0 = 0.f, s1 = 0.f;
#pragma unroll
        for (int j = 0; j < 8; ++j) {
            float p0 = exp2f(sfr[j][0] - mx0);
            float p1 = exp2f(sfr[j][1] - mx0);
            float p2 = exp2f(sfr[j][2] - mx1);
            float p3 = exp2f(sfr[j][3] - mx1);
            sfr[j][0] = p0; sfr[j][1] = p1; sfr[j][2] = p2; sfr[j][3] = p3;
            s0 += p0 + p1; s1 += p2 + p3;
        }
        s0 += __shfl_xor_sync(0xffffffffu, s0, 1);
        s0 += __shfl_xor_sync(0xffffffffu, s0, 2);
        s1 += __shfl_xor_sync(0xffffffffu, s1, 1);
        s1 += __shfl_xor_sync(0xffffffffu, s1, 2);
        l0 = l0 * al0 + s0;
        l1 = l1 * al1 + s1;
#pragma unroll
        for (int j = 0; j < 8; ++j) {
            oac[j][0] *= al0; oac[j][1] *= al0;
            oac[j][2] *= al1; oac[j][3] *= al1;
        }

        // ---- O += P @ V (bf16x3; P frags from S-accumulator layout) ----
#pragma unroll
        for (int t = 0; t < 4; ++t) {
            const float* f0 = sfr[2*t];
            const float* f1 = sfr[2*t+1];
            uint32_t pah[4], pal[4];
            pah[0] = packbf(f0[0], f0[1]);
            pah[1] = packbf(f0[2], f0[3]);
            pah[2] = packbf(f1[0], f1[1]);
            pah[3] = packbf(f1[2], f1[3]);
            pal[0] = packbf(bfres(f0[0]), bfres(f0[1]));
            pal[1] = packbf(bfres(f0[2]), bfres(f0[3]));
            pal[2] = packbf(bfres(f1[0]), bfres(f1[1]));
            pal[3] = packbf(bfres(f1[2]), bfres(f1[3]));
#pragma unroll
            for (int np = 0; np < 4; ++np) {
                uint32_t vbh[4], vbl[4];
                const uint32_t va = (t * 16 + vrow) * AROWB + np * 32 + vof;
                ldsm_x4_t(vbh, sVh + va);
                ldsm_x4_t(vbl, sVl + va);
                mma16816(oac[2*np],   pah, vbh);
                mma16816(oac[2*np],   pal, vbh);
                mma16816(oac[2*np],   pah, vbl);
                mma16816(oac[2*np+1], pah, vbh + 2);
                mma16816(oac[2*np+1], pal, vbh + 2);
                mma16816(oac[2*np+1], pah, vbl + 2);
            }
        }
    }

    // ---- write O (bf16 hi/lo) ----
    const float inv0 = 1.f / l0, inv1 = 1.f / l1;
    const int r0g = q0 + warp * 16 + (lane >> 2);
#pragma unroll
    for (int j = 0; j < 8; ++j) {
        const size_t off0 = base + (size_t)r0g * DD + j * 8 + 2 * (lane & 3);
        const size_t off1 = off0 + (size_t)8 * DD;
        const float v0 = oac[j][0] * inv0, v1 = oac[j][1] * inv0;
        const float v2 = oac[j][2] * inv1, v3 = oac[j][3] * inv1;
        __nv_bfloat16 h0 = __float2bfloat16(v0), h1 = __float2bfloat16(v1);
        __nv_bfloat16 h2 = __float2bfloat16(v2), h3 = __float2bfloat16(v3);
        *(__nv_bfloat162*)(ohi + off0) = __halves2bfloat162(h0, h1);
        *(__nv_bfloat162*)(ohi + off1) = __halves2bfloat162(h2, h3);
        *(__nv_bfloat162*)(olo + off0) = __halves2bfloat162(
            __float2bfloat16(v0 - __bfloat162float(h0)),
            __float2bfloat16(v1 - __bfloat162float(h1)));
        *(__nv_bfloat162*)(olo + off1) = __halves2bfloat162(
            __float2bfloat16(v2 - __bfloat162float(h2)),
            __float2bfloat16(v3 - __bfloat162float(h3)));
    }
}

// ---------------- host launcher -------------------------------------------------
extern "C" void kernel_launch(void* const* d_in, const int* in_sizes, int n_in,
                              void* d_out, int out_size) {
    const float* x     = (const float*)d_in[0];
    const float* ln1_g = (const float*)d_in[1];
    const float* ln1_b = (const float*)d_in[2];
    const float* wq    = (const float*)d_in[3];
    const float* bq    = (const float*)d_in[4];
    const float* wk    = (const float*)d_in[5];
    const float* bk    = (const float*)d_in[6];
    const float* wv    = (const float*)d_in[7];
    const float* bv    = (const float*)d_in[8];
    const float* wo    = (const float*)d_in[9];
    const float* bo    = (const float*)d_in[10];
    const float* ln2_g = (const float*)d_in[11];
    const float* ln2_b = (const float*)d_in[12];
    const float* w1    = (const float*)d_in[13];
    const float* b1    = (const float*)d_in[14];
    const float* w2    = (const float*)d_in[15];
    const float* b2    = (const float*)d_in[16];
    float* out = (float*)d_out;

    __nv_bfloat16 *hhi, *hlo, *qhi, *qlo, *khi, *klo, *vhi, *vlo, *ohi, *olo;
    __nv_bfloat16 *h2hi, *h2lo, *acthi, *actlo;
    __nv_bfloat16 *wqh, *wql, *wkh, *wkl, *wvh, *wvl, *woh, *wol, *w1h, *w1l, *w2h, *w2l;
    float *padd1;
    cudaGetSymbolAddress((void**)&hhi,  g_h_hi);  cudaGetSymbolAddress((void**)&hlo,  g_h_lo);
    cudaGetSymbolAddress((void**)&qhi,  g_q_hi);  cudaGetSymbolAddress((void**)&qlo,  g_q_lo);
    cudaGetSymbolAddress((void**)&khi,  g_k_hi);  cudaGetSymbolAddress((void**)&klo,  g_k_lo);
    cudaGetSymbolAddress((void**)&vhi,  g_v_hi);  cudaGetSymbolAddress((void**)&vlo,  g_v_lo);
    cudaGetSymbolAddress((void**)&ohi,  g_o_hi);  cudaGetSymbolAddress((void**)&olo,  g_o_lo);
    cudaGetSymbolAddress((void**)&padd1,g_add1);
    cudaGetSymbolAddress((void**)&h2hi, g_h2_hi); cudaGetSymbolAddress((void**)&h2lo, g_h2_lo);
    cudaGetSymbolAddress((void**)&acthi,g_act_hi);cudaGetSymbolAddress((void**)&actlo,g_act_lo);
    cudaGetSymbolAddress((void**)&wqh,  g_wq_hi); cudaGetSymbolAddress((void**)&wql,  g_wq_lo);
    cudaGetSymbolAddress((void**)&wkh,  g_wk_hi); cudaGetSymbolAddress((void**)&wkl,  g_wk_lo);
    cudaGetSymbolAddress((void**)&wvh,  g_wv_hi); cudaGetSymbolAddress((void**)&wvl,  g_wv_lo);
    cudaGetSymbolAddress((void**)&woh,  g_wo_hi); cudaGetSymbolAddress((void**)&wol,  g_wo_lo);
    cudaGetSymbolAddress((void**)&w1h,  g_w1_hi); cudaGetSymbolAddress((void**)&w1l,  g_w1_lo);
    cudaGetSymbolAddress((void**)&w2h,  g_w2_hi); cudaGetSymbolAddress((void**)&w2l,  g_w2_lo);

    cudaFuncSetAttribute(tc_gemm<0,false,false>, cudaFuncAttributeMaxDynamicSharedMemorySize, GEMM_SMEM);
    cudaFuncSetAttribute(tc_gemm<0,true, false>, cudaFuncAttributeMaxDynamicSharedMemorySize, GEMM_SMEM);
    cudaFuncSetAttribute(tc_gemm<1,false,false>, cudaFuncAttributeMaxDynamicSharedMemorySize, GEMM_SMEM);
    cudaFuncSetAttribute(tc_gemm<1,false,true >, cudaFuncAttributeMaxDynamicSharedMemorySize, GEMM_SMEM);
    cudaFuncSetAttribute(attn_mma, cudaFuncAttributeMaxDynamicSharedMemorySize, ATT_SMEM);

    // weight transpose + bf16 split
    wsplit_kernel<<<dim3(DD/32, DD/32), 256>>>(wq, wqh, wql, DD, DD);
    wsplit_kernel<<<dim3(DD/32, DD/32), 256>>>(wk, wkh, wkl, DD, DD);
    wsplit_kernel<<<dim3(DD/32, DD/32), 256>>>(wv, wvh, wvl, DD, DD);
    wsplit_kernel<<<dim3(DD/32, DD/32), 256>>>(wo, woh, wol, DD, DD);
    wsplit_kernel<<<dim3(FF/32, DD/32), 256>>>(w1, w1h, w1l, DD, FF);
    wsplit_kernel<<<dim3(DD/32, FF/32), 256>>>(w2, w2h, w2l, FF, DD);

    // ln1 -> bf16 split
    ln_split_kernel<<<NTOK, 256>>>(x, ln1_g, ln1_b, hhi, hlo);

    // QKV projections -> bf16 hi/lo
    {
        dim3 grid(DD/128, NTOK/128);
        tc_gemm<1,false,false><<<grid, 256, GEMM_SMEM>>>(hhi, hlo, wqh, wql, bq, nullptr, nullptr, qhi, qlo, NTOK, DD, DD);
        tc_gemm<1,false,false><<<grid, 256, GEMM_SMEM>>>(hhi, hlo, wkh, wkl, bk, nullptr, nullptr, khi, klo, NTOK, DD, DD);
        tc_gemm<1,false,false><<<grid, 256, GEMM_SMEM>>>(hhi, hlo, wvh, wvl, bv, nullptr, nullptr, vhi, vlo, NTOK, DD, DD);
    }

    // attention (tensor-core flash)
    {
        dim3 grid(SS/128, BB*HH);
        attn_mma<<<grid, 256, ATT_SMEM>>>(qhi, qlo, khi, klo, vhi, vlo, ohi, olo);
    }

    // O-proj + residual: add1 = x + o@wo + bo
    {
        dim3 grid(DD/128, NTOK/128);
        tc_gemm<0,true,false><<<grid, 256, GEMM_SMEM>>>(ohi, olo, woh, wol, bo, x, padd1, nullptr, nullptr, NTOK, DD, DD);
    }

    // ln2 -> bf16 split
    ln_split_kernel<<<NTOK, 256>>>(padd1, ln2_g, ln2_b, h2hi, h2lo);

    // MLP up + gelu -> bf16 pair
    {
        dim3 grid(FF/128, NTOK/128);
        tc_gemm<1,false,true><<<grid, 256, GEMM_SMEM>>>(h2hi, h2lo, w1h, w1l, b1, nullptr, nullptr, acthi, actlo, NTOK, FF, DD);
    }

    // MLP down + residual -> out
    {
        dim3 grid(DD/128, NTOK/128);
        tc_gemm<0,true,false><<<grid, 256, GEMM_SMEM>>>(acthi, actlo, w2h, w2l, b2, padd1, out, nullptr, nullptr, NTOK, DD, FF);
    }
}